// round 14
// baseline (speedup 1.0000x reference)
#include <cuda_runtime.h>
#include <math.h>

#define T_   2048
#define B_   8
#define D_   1024
#define HD   64      // d
#define NM_  8
#define MP1  9
#define NT   (T_*B_)     // 16384 tokens
#define NKV  576         // Mp1 * d

// ---------------- static device scratch ----------------
__device__ float g_Q[NT*HD];                                // tf32-valued fp32
__device__ float g_Kp[(size_t)B_*MP1*T_*HD];                // packed K per (b,m), tf32-valued
__device__ float g_Vp[(size_t)B_*MP1*T_*HD];                // packed V per (b,m), tf32-valued
#define NSLOT (B_*MP1*32)
__device__ float g_G[(size_t)(NSLOT + 16)*HD*HD];           // per-chunk K^T V (+16 slot pad for prefetch)
__device__ float g_S[(size_t)NSLOT*HD*HD];                  // chunk start state (tf32-valued)
__device__ int   g_tok[B_*NM_*T_];
__device__ float g_pa [B_*NM_*T_];
__device__ int   g_cnt[B_*NM_];
__device__ unsigned char g_m1[NT], g_m2[NT];
__device__ float g_a1[NT], g_a2[NT];
__device__ unsigned g_Xt[(size_t)NT*D_];                    // X in tf32 bits
__device__ unsigned g_Wqt[D_*HD];
__device__ unsigned g_Wkt[D_*NKV];
__device__ unsigned g_Wvt[D_*NKV];

// ---------------- tf32 mma helpers ----------------
__device__ __forceinline__ unsigned f2tf32(float f) {
    unsigned u;
    asm("cvt.rna.tf32.f32 %0, %1;" : "=r"(u) : "f"(f));
    return u;
}
__device__ __forceinline__ float f2tf32f(float f) { return __uint_as_float(f2tf32(f)); }
__device__ __forceinline__ void mma_tf32(float* c,
    unsigned a0, unsigned a1, unsigned a2, unsigned a3,
    unsigned b0, unsigned b1)
{
    asm volatile(
        "mma.sync.aligned.m16n8k8.row.col.f32.tf32.tf32.f32 "
        "{%0,%1,%2,%3}, {%4,%5,%6,%7}, {%8,%9}, {%0,%1,%2,%3};"
        : "+f"(c[0]), "+f"(c[1]), "+f"(c[2]), "+f"(c[3])
        : "r"(a0), "r"(a1), "r"(a2), "r"(a3), "r"(b0), "r"(b1));
}
__device__ __forceinline__ void cp16(void* dst, const void* src) {
    unsigned s = (unsigned)__cvta_generic_to_shared(dst);
    asm volatile("cp.async.cg.shared.global [%0], [%1], 16;" :: "r"(s), "l"(src));
}
__device__ __forceinline__ void cp16z(void* dst, const void* src, unsigned sz) {
    unsigned s = (unsigned)__cvta_generic_to_shared(dst);
    asm volatile("cp.async.cg.shared.global [%0], [%1], 16, %2;" :: "r"(s), "l"(src), "r"(sz));
}
#define CP_COMMIT() asm volatile("cp.async.commit_group;" ::)
#define CP_WAIT1()  asm volatile("cp.async.wait_group 1;" ::)
#define CP_WAIT0()  asm volatile("cp.async.wait_group 0;" ::)

// ---------------- fused prep: gate (+tf32 X) | zero out | weight convert ----------------
#define GATE_BLKS 2048
#define ZERO_BLKS 1024
#define WCONV_BLKS 2304
__global__ __launch_bounds__(256) void prep_kernel(
    const float* __restrict__ X, const float* __restrict__ Wg, const float* __restrict__ bg,
    const float* __restrict__ Wq, const float* __restrict__ Wk, const float* __restrict__ Wv,
    float* __restrict__ out)
{
    int bx = blockIdx.x;
    if (bx >= GATE_BLKS) {
        if (bx < GATE_BLKS + ZERO_BLKS) {
            int i = (bx - GATE_BLKS) * 256 + threadIdx.x;
            reinterpret_cast<float4*>(out)[i] = make_float4(0.f, 0.f, 0.f, 0.f);
        } else {
            int i = (bx - GATE_BLKS - ZERO_BLKS) * 256 + threadIdx.x;
            if (i < D_*HD) g_Wqt[i] = f2tf32(Wq[i]);
            g_Wkt[i] = f2tf32(Wk[i]);
            g_Wvt[i] = f2tf32(Wv[i]);
        }
        return;
    }
    int warp = (bx * 256 + threadIdx.x) >> 5;
    int lane = threadIdx.x & 31;
    const float* x = X + (size_t)warp * D_;
    float s[8];
    #pragma unroll
    for (int j = 0; j < 8; j++) s[j] = 0.f;
    for (int i = lane; i < D_; i += 32) {
        float xv = x[i];
        g_Xt[(size_t)warp*D_ + i] = f2tf32(xv);
        float4 w0 = *reinterpret_cast<const float4*>(Wg + (size_t)i*8);
        float4 w1 = *reinterpret_cast<const float4*>(Wg + (size_t)i*8 + 4);
        s[0] = fmaf(xv, w0.x, s[0]); s[1] = fmaf(xv, w0.y, s[1]);
        s[2] = fmaf(xv, w0.z, s[2]); s[3] = fmaf(xv, w0.w, s[3]);
        s[4] = fmaf(xv, w1.x, s[4]); s[5] = fmaf(xv, w1.y, s[5]);
        s[6] = fmaf(xv, w1.z, s[6]); s[7] = fmaf(xv, w1.w, s[7]);
    }
    #pragma unroll
    for (int off = 16; off > 0; off >>= 1)
        #pragma unroll
        for (int j = 0; j < 8; j++)
            s[j] += __shfl_xor_sync(0xffffffffu, s[j], off);
    if (lane == 0) {
        #pragma unroll
        for (int j = 0; j < 8; j++) s[j] += bg[j];
        int i1 = 0;
        #pragma unroll
        for (int j = 1; j < 8; j++) if (s[j] > s[i1]) i1 = j;
        int i2 = -1; float b2 = -1e30f;
        #pragma unroll
        for (int j = 0; j < 8; j++) if (j != i1 && s[j] > b2) { b2 = s[j]; i2 = j; }
        float a1 = 1.f / (1.f + expf(b2 - s[i1]));
        g_m1[warp] = (unsigned char)(i1 + 1);
        g_m2[warp] = (unsigned char)(i2 + 1);
        g_a1[warp] = a1;
        g_a2[warp] = 1.f - a1;
    }
}

// ---------------- pack: 1024 threads, 2 sweep iterations ----------------
__global__ __launch_bounds__(1024) void pack_kernel()
{
    int bm = blockIdx.x;          // 0..63
    int b  = bm >> 3;
    int m  = (bm & 7) + 1;        // 1..8
    __shared__ int wsum[32];
    int tid = threadIdx.x;
    int lane = tid & 31, w = tid >> 5;
    int base = 0;
    int segbase = (b*NM_ + m - 1) * T_;
    for (int t0 = 0; t0 < T_; t0 += 1024) {
        int t = t0 + tid;
        int n = t*B_ + b;
        int sel = 0; float a = 0.f;
        int m1v = g_m1[n], m2v = g_m2[n];
        if      (m1v == m) { sel = 1; a = g_a1[n]; }
        else if (m2v == m) { sel = 1; a = g_a2[n]; }
        int incl = sel;
        #pragma unroll
        for (int off = 1; off < 32; off <<= 1) {
            int u = __shfl_up_sync(0xffffffffu, incl, off);
            if (lane >= off) incl += u;
        }
        if (lane == 31) wsum[w] = incl;
        __syncthreads();
        int woff = 0, tot = 0;
        #pragma unroll
        for (int i = 0; i < 32; i++) { int v = wsum[i]; tot += v; if (i < w) woff += v; }
        if (sel) {
            int pos = base + woff + incl - 1;
            g_tok[segbase + pos] = t;
            g_pa [segbase + pos] = a;
        }
        base += tot;
        __syncthreads();
    }
    if (tid == 0) g_cnt[b*NM_ + m - 1] = base;
}

// ---------------- fused projections: KV tiles (256 rows, 512 thr) + Q tile pairs ----------------
#define KV_AP 20
#define KV_BP 136
#define KV_SMEM ((3*256*KV_AP + 3*16*KV_BP + 256) * 4)
#define Q_AP 20
#define Q_BP 72
#define Q_WORDS (3*64*Q_AP + 3*16*Q_BP)
#define GP_ 68

__device__ __forceinline__ void proj_q_body(unsigned* smem, const float* bq, int bx, int tid)
{
    unsigned (*As)[64][Q_AP] = reinterpret_cast<unsigned(*)[64][Q_AP]>(smem);
    unsigned (*Bs)[16][Q_BP] = reinterpret_cast<unsigned(*)[16][Q_BP]>(smem + 3*64*Q_AP);
    int m0 = bx * 64;

    int aRow = (tid & 127) >> 1, aOff = (tid & 1) * 8;
    int t2 = tid & 127;
    int bK = t2 >> 3, bj = (t2 & 7) * 8;
    const unsigned* aBase = g_Xt + (size_t)(m0 + aRow)*D_ + aOff;
    const unsigned* bBase = g_Wqt + (size_t)bK*HD + bj;
    bool isA = (tid < 128);

    int lane = tid & 31, gid = lane >> 2, tig = lane & 3;
    int warpId = tid >> 5, wM = warpId & 3, wN = warpId >> 2;

    float c[4][4];
    #pragma unroll
    for (int ni = 0; ni < 4; ni++)
        #pragma unroll
        for (int j = 0; j < 4; j++) c[ni][j] = 0.f;

    #pragma unroll
    for (int s = 0; s < 2; s++) {
        int kt = s * 16;
        if (isA) {
            cp16(&As[s][aRow][aOff],     aBase + kt);
            cp16(&As[s][aRow][aOff + 4], aBase + kt + 4);
        } else {
            cp16(&Bs[s][bK][bj],     bBase + (size_t)kt*HD);
            cp16(&Bs[s][bK][bj + 4], bBase + (size_t)kt*HD + 4);
        }
        CP_COMMIT();
    }

    for (int it = 0; it < 64; it++) {
        CP_WAIT1();
        __syncthreads();
        if (it + 2 < 64) {
            int s = (it + 2) % 3, kt = (it + 2) * 16;
            if (isA) {
                cp16(&As[s][aRow][aOff],     aBase + kt);
                cp16(&As[s][aRow][aOff + 4], aBase + kt + 4);
            } else {
                cp16(&Bs[s][bK][bj],     bBase + (size_t)kt*HD);
                cp16(&Bs[s][bK][bj + 4], bBase + (size_t)kt*HD + 4);
            }
        }
        CP_COMMIT();
        int s = it % 3;
        #pragma unroll
        for (int k0 = 0; k0 < 16; k0 += 8) {
            int r = wM*16 + gid;
            unsigned a0 = As[s][r    ][k0 + tig];
            unsigned a1 = As[s][r + 8][k0 + tig];
            unsigned a2 = As[s][r    ][k0 + tig + 4];
            unsigned a3 = As[s][r + 8][k0 + tig + 4];
            #pragma unroll
            for (int ni = 0; ni < 4; ni++) {
                int cb = wN*32 + ni*8 + gid;
                unsigned b0 = Bs[s][k0 + tig    ][cb];
                unsigned b1 = Bs[s][k0 + tig + 4][cb];
                mma_tf32(c[ni], a0, a1, a2, a3, b0, b1);
            }
        }
    }

    #pragma unroll
    for (int ni = 0; ni < 4; ni++) {
        int colb = wN*32 + ni*8 + tig*2;
        float b0v = bq[colb], b1v = bq[colb + 1];
        int r1 = m0 + wM*16 + gid;
        float2 v1 = make_float2(f2tf32f(c[ni][0] + b0v), f2tf32f(c[ni][1] + b1v));
        *reinterpret_cast<float2*>(g_Q + (size_t)r1*HD + colb) = v1;
        float2 v2 = make_float2(f2tf32f(c[ni][2] + b0v), f2tf32f(c[ni][3] + b1v));
        *reinterpret_cast<float2*>(g_Q + (size_t)(r1 + 8)*HD + colb) = v2;
    }
}

__device__ __forceinline__ void proj_kv_body(unsigned* smem,
    const float* bk, const float* bv, int ci, int m, int b)
{
    int cnt = (m == 0) ? T_ : g_cnt[b*NM_ + m - 1];
    int r0 = ci << 8;
    if (r0 >= cnt) return;
    int L = cnt - r0; if (L > 256) L = 256;

    unsigned (*As)[256][KV_AP] = reinterpret_cast<unsigned(*)[256][KV_AP]>(smem);
    unsigned (*Bs)[16][KV_BP]  = reinterpret_cast<unsigned(*)[16][KV_BP]>(smem + 3*256*KV_AP);
    int* rowIdx = reinterpret_cast<int*>(smem + 3*256*KV_AP + 3*16*KV_BP);

    int tid = threadIdx.x;
    int segbase = (b*NM_ + m - 1) * T_;
    if (tid < 256) {
        int t = 0;
        if (tid < L) t = (m == 0) ? (r0 + tid) : g_tok[segbase + r0 + tid];
        rowIdx[tid] = t*B_ + b;
    }
    __syncthreads();

    // cp.async mapping: A 256 rows x 16 k (2 cp16/thread); B 16 k x 128 cols (1 cp16/thread)
    int aRow = tid >> 1, aOff = (tid & 1) * 8;
    int bK   = tid >> 5;                 // 0..15
    int bj   = (tid & 31) * 4;           // 0..124
    int bHalf = bj >> 6;
    int bo    = bj & 63;
    const unsigned* Wt = bHalf ? g_Wvt : g_Wkt;
    const unsigned* aBase = g_Xt + (size_t)rowIdx[aRow]*D_ + aOff;
    const unsigned* bBase = Wt + (size_t)bK*NKV + m*HD + bo;

    int lane = tid & 31, gid = lane >> 2, tig = lane & 3;
    int warpId = tid >> 5, wM = warpId & 3, wN = warpId >> 2;  // 4(M) x 4(N)

    float c[4][4][4];
    #pragma unroll
    for (int mi = 0; mi < 4; mi++)
        #pragma unroll
        for (int ni = 0; ni < 4; ni++)
            #pragma unroll
            for (int j = 0; j < 4; j++) c[mi][ni][j] = 0.f;

    #pragma unroll
    for (int s = 0; s < 2; s++) {
        int kt = s * 16;
        cp16(&As[s][aRow][aOff],     aBase + kt);
        cp16(&As[s][aRow][aOff + 4], aBase + kt + 4);
        cp16(&Bs[s][bK][bj],         bBase + (size_t)kt*NKV);
        CP_COMMIT();
    }

    for (int it = 0; it < 64; it++) {
        CP_WAIT1();
        __syncthreads();
        if (it + 2 < 64) {
            int s = (it + 2) % 3, kt = (it + 2) * 16;
            cp16(&As[s][aRow][aOff],     aBase + kt);
            cp16(&As[s][aRow][aOff + 4], aBase + kt + 4);
            cp16(&Bs[s][bK][bj],         bBase + (size_t)kt*NKV);
        }
        CP_COMMIT();
        int s = it % 3;
        #pragma unroll
        for (int k0 = 0; k0 < 16; k0 += 8) {
            unsigned a[4][4];
            #pragma unroll
            for (int mi = 0; mi < 4; mi++) {
                int r = wM*64 + mi*16 + gid;
                a[mi][0] = As[s][r    ][k0 + tig];
                a[mi][1] = As[s][r + 8][k0 + tig];
                a[mi][2] = As[s][r    ][k0 + tig + 4];
                a[mi][3] = As[s][r + 8][k0 + tig + 4];
            }
            #pragma unroll
            for (int ni = 0; ni < 4; ni++) {
                int cb = wN*32 + ni*8 + gid;
                unsigned b0 = Bs[s][k0 + tig    ][cb];
                unsigned b1 = Bs[s][k0 + tig + 4][cb];
                #pragma unroll
                for (int mi = 0; mi < 4; mi++)
                    mma_tf32(c[mi][ni], a[mi][0], a[mi][1], a[mi][2], a[mi][3], b0, b1);
            }
        }
    }

    // ---- global K/V stores ----
    size_t segKV = ((size_t)(b*MP1 + m)*T_ + r0) * HD;
    #pragma unroll
    for (int mi = 0; mi < 4; mi++) {
        #pragma unroll
        for (int ni = 0; ni < 4; ni++) {
            int colb = wN*32 + ni*8 + tig*2;
            int half = colb >> 6;
            int cc = colb & 63;
            const float* bias = half ? bv : bk;
            float b0v = bias[m*HD + cc];
            float b1v = bias[m*HD + cc + 1];
            float* dst = (half ? g_Vp : g_Kp) + segKV + cc;
            int r1 = wM*64 + mi*16 + gid;
            if (r1 < L) {
                float2 v = make_float2(f2tf32f(c[mi][ni][0] + b0v), f2tf32f(c[mi][ni][1] + b1v));
                *reinterpret_cast<float2*>(dst + (size_t)r1*HD) = v;
            }
            int r2 = r1 + 8;
            if (r2 < L) {
                float2 v = make_float2(f2tf32f(c[mi][ni][2] + b0v), f2tf32f(c[mi][ni][3] + b1v));
                *reinterpret_cast<float2*>(dst + (size_t)r2*HD) = v;
            }
        }
    }

    // ---- fused G = K^T V per 64-chunk (4 chunks; reuses pipeline smem) ----
    float* fb = reinterpret_cast<float*>(smem);
    float (*Ks)[GP_] = reinterpret_cast<float(*)[GP_]>(fb);
    float (*Vs)[GP_] = reinterpret_cast<float(*)[GP_]>(fb + 64*GP_);
    int nchunk = (L + 63) >> 6;

    for (int cp = 0; cp < nchunk; cp++) {
        __syncthreads();
        if (wM == cp) {          // 4 warps (wN 0..3) own rows [cp*64, cp*64+64)
            #pragma unroll
            for (int mi = 0; mi < 4; mi++) {
                #pragma unroll
                for (int ni = 0; ni < 4; ni++) {
                    int colb = wN*32 + ni*8 + tig*2;
                    int half = colb >> 6;
                    int cc = colb & 63;
                    const float* bias = half ? bv : bk;
                    float b0v = bias[m*HD + cc];
                    float b1v = bias[m*HD + cc + 1];
                    float (*Ts)[GP_] = half ? Vs : Ks;
                    int lr1 = mi*16 + gid;
                    int gr1 = cp*64 + lr1;
                    Ts[lr1][cc]     = (gr1 < L) ? f2tf32f(c[mi][ni][0] + b0v) : 0.f;
                    Ts[lr1][cc + 1] = (gr1 < L) ? f2tf32f(c[mi][ni][1] + b1v) : 0.f;
                    int lr2 = lr1 + 8, gr2 = gr1 + 8;
                    Ts[lr2][cc]     = (gr2 < L) ? f2tf32f(c[mi][ni][2] + b0v) : 0.f;
                    Ts[lr2][cc + 1] = (gr2 < L) ? f2tf32f(c[mi][ni][3] + b1v) : 0.f;
                }
            }
        }
        __syncthreads();

        // 16 warps compute 64x64 G; warp tile 16(M) x 16(N)
        float g[2][4];
        #pragma unroll
        for (int ni = 0; ni < 2; ni++)
            #pragma unroll
            for (int j = 0; j < 4; j++) g[ni][j] = 0.f;
        int i0 = wM*16, j0g = wN*16;
        #pragma unroll
        for (int k0 = 0; k0 < 64; k0 += 8) {
            unsigned a0 = __float_as_uint(Ks[k0 + tig    ][i0 + gid]);
            unsigned a1 = __float_as_uint(Ks[k0 + tig    ][i0 + gid + 8]);
            unsigned a2 = __float_as_uint(Ks[k0 + tig + 4][i0 + gid]);
            unsigned a3 = __float_as_uint(Ks[k0 + tig + 4][i0 + gid + 8]);
            #pragma unroll
            for (int ni = 0; ni < 2; ni++) {
                int cb = j0g + ni*8 + gid;
                unsigned b0 = __float_as_uint(Vs[k0 + tig    ][cb]);
                unsigned b1 = __float_as_uint(Vs[k0 + tig + 4][cb]);
                mma_tf32(g[ni], a0, a1, a2, a3, b0, b1);
            }
        }
        float* Gp = g_G + (size_t)((b*MP1 + m)*32 + ci*4 + cp) * 4096;
        #pragma unroll
        for (int ni = 0; ni < 2; ni++) {
            int j = j0g + ni*8 + tig*2;
            *reinterpret_cast<float2*>(Gp + (i0 + gid)*64 + j)     = make_float2(g[ni][0], g[ni][1]);
            *reinterpret_cast<float2*>(Gp + (i0 + gid + 8)*64 + j) = make_float2(g[ni][2], g[ni][3]);
        }
    }
}

#define KV_BLKS (8*MP1*B_)
__global__ __launch_bounds__(512, 1) void proj_kernel(
    const float* __restrict__ bq, const float* __restrict__ bk, const float* __restrict__ bv)
{
    extern __shared__ __align__(16) unsigned smem[];
    int bx = blockIdx.x;
    if (bx < KV_BLKS) {
        int ci = bx & 7;
        int rem = bx >> 3;
        int m = rem % MP1, b = rem / MP1;
        proj_kv_body(smem, bk, bv, ci, m, b);
    } else {
        int half = threadIdx.x >> 8;
        int qi = (bx - KV_BLKS)*2 + half;
        proj_q_body(smem + half*Q_WORDS, bq, qi, threadIdx.x & 255);
    }
}

// ---------------- per-segment prefix: 8-deep prefetch, tf32-rounded S ----------------
__global__ __launch_bounds__(256) void prefix_kernel(const float* __restrict__ M0)
{
    int bm = blockIdx.x;               // 0..71
    int b = bm / MP1, m = bm % MP1;
    int cnt = (m == 0) ? T_ : g_cnt[b*NM_ + m - 1];
    int nch = (cnt + 63) >> 6;
    int idx = blockIdx.y * 256 + threadIdx.x;   // 0..4095
    float st = M0[idx];
    const float* Gp = g_G + (size_t)(bm * 32) * 4096 + idx;
    float* Sp = g_S + (size_t)(bm * 32) * 4096 + idx;
    float p[8];
    #pragma unroll
    for (int j = 0; j < 8; j++) p[j] = Gp[(size_t)j * 4096];
    int ci = 0;
    for (; ci + 8 <= nch; ci += 8) {
        size_t off = (size_t)ci * 4096;
        float n[8];
        #pragma unroll
        for (int j = 0; j < 8; j++) n[j] = Gp[off + (size_t)(j + 8) * 4096];
        #pragma unroll
        for (int j = 0; j < 8; j++) {
            Sp[off + (size_t)j * 4096] = f2tf32f(st);
            st += p[j];
        }
        #pragma unroll
        for (int j = 0; j < 8; j++) p[j] = n[j];
    }
    for (; ci < nch; ci++) {
        size_t off = (size_t)ci * 4096;
        Sp[off] = f2tf32f(st);
        st += Gp[off];
    }
}

// ---------------- per-chunk output via tf32 mma: O = tril(QK^T)V + Q S ----------------
#define OP_ 68
#define O_SMEM (4*64*OP_*4)
__global__ __launch_bounds__(256, 2) void chunk_o_kernel(float* __restrict__ out)
{
    int ci = blockIdx.x, m = blockIdx.y, b = blockIdx.z;
    int cnt = (m == 0) ? T_ : g_cnt[b*NM_ + m - 1];
    if ((ci << 6) >= cnt) return;
    int L = cnt - (ci << 6); if (L > 64) L = 64;

    extern __shared__ __align__(16) float sm[];
    float (*QS)[OP_] = reinterpret_cast<float(*)[OP_]>(sm);            // Q
    float (*KP)[OP_] = reinterpret_cast<float(*)[OP_]>(sm + 64*OP_);   // K, then P
    float (*Vs)[OP_] = reinterpret_cast<float(*)[OP_]>(sm + 2*64*OP_); // V
    float (*Ss)[OP_] = reinterpret_cast<float(*)[OP_]>(sm + 3*64*OP_); // S

    int tid = threadIdx.x;
    int segbase = (m == 0) ? 0 : (b*NM_ + m - 1)*T_;
    size_t segp = ((size_t)(b*MP1 + m)*T_ + (ci << 6)) * HD;

    // group 0: Q/K/V via cp.async (zfill for invalid rows)
    {
        int r = tid >> 2, q4 = tid & 3;
        bool valid = r < L;
        const float* qs = g_Q;
        if (valid) {
            int i = (ci << 6) + r;
            int t = (m == 0) ? i : g_tok[segbase + i];
            qs = g_Q + ((size_t)t*B_ + b)*HD;
        }
        const float* ks = g_Kp + segp + (size_t)r*HD;
        const float* vs = g_Vp + segp + (size_t)r*HD;
        unsigned sz = valid ? 16u : 0u;
        #pragma unroll
        for (int j = 0; j < 4; j++) {
            int c = q4*16 + j*4;
            cp16z(&QS[r][c], qs + c, sz);
            cp16z(&KP[r][c], ks + c, sz);
            cp16z(&Vs[r][c], vs + c, sz);
        }
        CP_COMMIT();
    }
    // group 1: S prefetch
    {
        const float* Sp = g_S + (size_t)((b*MP1 + m)*32 + ci) * 4096;
        #pragma unroll
        for (int i = 0; i < 4; i++) {
            int k = tid + i*256;
            int r = k >> 4, cc = (k & 15) * 4;
            cp16(&Ss[r][cc], Sp + r*64 + cc);
        }
        CP_COMMIT();
    }

    CP_WAIT1();
    __syncthreads();

    int lane = tid & 31, gid = lane >> 2, tig = lane & 3;
    int warpId = tid >> 5, wM = warpId & 3, wN = warpId >> 2;
    int r0 = wM*16, n0 = wN*32;

    unsigned aQ[8][4];
    #pragma unroll
    for (int ks = 0; ks < 8; ks++) {
        int k0 = ks*8;
        aQ[ks][0] = __float_as_uint(QS[r0 + gid    ][k0 + tig]);
        aQ[ks][1] = __float_as_uint(QS[r0 + gid + 8][k0 + tig]);
        aQ[ks][2] = __float_as_uint(QS[r0 + gid    ][k0 + tig + 4]);
        aQ[ks][3] = __float_as_uint(QS[r0 + gid + 8][k0 + tig + 4]);
    }

    // stage 1: P = Q K^T
    float p[4][4];
    #pragma unroll
    for (int ni = 0; ni < 4; ni++)
        #pragma unroll
        for (int j = 0; j < 4; j++) p[ni][j] = 0.f;
    #pragma unroll
    for (int ks = 0; ks < 8; ks++) {
        int k0 = ks*8;
        #pragma unroll
        for (int ni = 0; ni < 4; ni++) {
            int cb = n0 + ni*8 + gid;
            unsigned b0 = __float_as_uint(KP[cb][k0 + tig]);
            unsigned b1 = __float_as_uint(KP[cb][k0 + tig + 4]);
            mma_tf32(p[ni], aQ[ks][0], aQ[ks][1], aQ[ks][2], aQ[ks][3], b0, b1);
        }
    }
    __syncthreads();

    // write masked tf32 P over K
    #pragma unroll
    for (int ni = 0; ni < 4; ni++) {
        int col = n0 + ni*8 + tig*2;
        int row1 = r0 + gid, row2 = r0 + gid + 8;
        KP[row1][col]     = (col     <= row1) ? f2tf32f(p[ni][0]) : 0.f;
        KP[row1][col + 1] = (col + 1 <= row1) ? f2tf32f(p[ni][1]) : 0.f;
        KP[row2][col]     = (col     <= row2) ? f2tf32f(p[ni][2]) : 0.f;
        KP[row2][col + 1] = (col + 1 <= row2) ? f2tf32f(p[ni][3]) : 0.f;
    }
    CP_WAIT0();
    __syncthreads();

    // stages 2+3: O = P V + Q S
    float o[4][4];
    #pragma unroll
    for (int ni = 0; ni < 4; ni++)
        #pragma unroll
        for (int j = 0; j < 4; j++) o[ni][j] = 0.f;
    #pragma unroll
    for (int ks = 0; ks < 8; ks++) {
        int k0 = ks*8;
        unsigned a0 = __float_as_uint(KP[r0 + gid    ][k0 + tig]);
        unsigned a1 = __float_as_uint(KP[r0 + gid + 8][k0 + tig]);
        unsigned a2 = __float_as_uint(KP[r0 + gid    ][k0 + tig + 4]);
        unsigned a3 = __float_as_uint(KP[r0 + gid + 8][k0 + tig + 4]);
        #pragma unroll
        for (int ni = 0; ni < 4; ni++) {
            int cb = n0 + ni*8 + gid;
            unsigned b0 = __float_as_uint(Vs[k0 + tig    ][cb]);
            unsigned b1 = __float_as_uint(Vs[k0 + tig + 4][cb]);
            mma_tf32(o[ni], a0, a1, a2, a3, b0, b1);
            unsigned s0 = __float_as_uint(Ss[k0 + tig    ][cb]);
            unsigned s1 = __float_as_uint(Ss[k0 + tig + 4][cb]);
            mma_tf32(o[ni], aQ[ks][0], aQ[ks][1], aQ[ks][2], aQ[ks][3], s0, s1);
        }
    }

    // epilogue: out[t,b,col..col+1] += alpha * o
    #pragma unroll
    for (int rr = 0; rr < 2; rr++) {
        int r = r0 + gid + rr*8;
        if (r >= L) continue;
        int idx = (ci << 6) + r;
        int t; float alpha;
        if (m == 0) { t = idx; alpha = 1.f; }
        else        { t = g_tok[segbase + idx]; alpha = g_pa[segbase + idx]; }
        float* op = out + ((size_t)t*B_ + b)*HD;
        #pragma unroll
        for (int ni = 0; ni < 4; ni++) {
            int col = n0 + ni*8 + tig*2;
            atomicAdd(op + col,     alpha * o[ni][rr*2]);
            atomicAdd(op + col + 1, alpha * o[ni][rr*2 + 1]);
        }
    }
}

// ---------------- launch ----------------
extern "C" void kernel_launch(void* const* d_in, const int* in_sizes, int n_in,
                              void* d_out, int out_size)
{
    const float* X  = (const float*)d_in[0];
    const float* M0 = (const float*)d_in[1];
    const float* Wq = (const float*)d_in[2];
    const float* bq = (const float*)d_in[3];
    const float* Wk = (const float*)d_in[4];
    const float* bk = (const float*)d_in[5];
    const float* Wv = (const float*)d_in[6];
    const float* bv = (const float*)d_in[7];
    const float* Wg = (const float*)d_in[8];
    const float* bg = (const float*)d_in[9];
    float* out = (float*)d_out;

    cudaFuncSetAttribute(proj_kernel,
                         cudaFuncAttributeMaxDynamicSharedMemorySize, KV_SMEM);
    cudaFuncSetAttribute(chunk_o_kernel,
                         cudaFuncAttributeMaxDynamicSharedMemorySize, O_SMEM);

    prep_kernel<<<GATE_BLKS + ZERO_BLKS + WCONV_BLKS, 256>>>(X, Wg, bg, Wq, Wk, Wv, out);
    pack_kernel<<<64, 1024>>>();
    proj_kernel<<<KV_BLKS + 128, 512, KV_SMEM>>>(bq, bk, bv);
    prefix_kernel<<<dim3(B_*MP1, 16), 256>>>(M0);
    chunk_o_kernel<<<dim3(32, MP1, B_), 256, O_SMEM>>>(out);
}

// round 15
// speedup vs baseline: 1.6186x; 1.6186x over previous
#include <cuda_runtime.h>
#include <math.h>

#define T_   2048
#define B_   8
#define D_   1024
#define HD   64      // d
#define NM_  8
#define MP1  9
#define NT   (T_*B_)     // 16384 tokens
#define NKV  576         // Mp1 * d

// ---------------- static device scratch ----------------
__device__ float g_Q[NT*HD];                                // tf32-valued fp32
__device__ float g_Kp[(size_t)B_*MP1*T_*HD];                // packed K per (b,m), tf32-valued
__device__ float g_Vp[(size_t)B_*MP1*T_*HD];                // packed V per (b,m), tf32-valued
#define NSLOT (B_*MP1*32)
__device__ float g_G[(size_t)(NSLOT + 16)*HD*HD];           // per-chunk K^T V (+16 slot pad for prefetch)
__device__ float g_S[(size_t)NSLOT*HD*HD];                  // chunk start state (tf32-valued)
__device__ int   g_tok[B_*NM_*T_];
__device__ float g_pa [B_*NM_*T_];
__device__ int   g_cnt[B_*NM_];
__device__ unsigned char g_m1[NT], g_m2[NT];
__device__ float g_a1[NT], g_a2[NT];
__device__ unsigned g_Xt[(size_t)NT*D_];                    // X in tf32 bits
__device__ unsigned g_Wqt[D_*HD];
__device__ unsigned g_Wkt[D_*NKV];
__device__ unsigned g_Wvt[D_*NKV];

// ---------------- tf32 mma helpers ----------------
__device__ __forceinline__ unsigned f2tf32(float f) {
    unsigned u;
    asm("cvt.rna.tf32.f32 %0, %1;" : "=r"(u) : "f"(f));
    return u;
}
__device__ __forceinline__ float f2tf32f(float f) { return __uint_as_float(f2tf32(f)); }
__device__ __forceinline__ void mma_tf32(float* c,
    unsigned a0, unsigned a1, unsigned a2, unsigned a3,
    unsigned b0, unsigned b1)
{
    asm volatile(
        "mma.sync.aligned.m16n8k8.row.col.f32.tf32.tf32.f32 "
        "{%0,%1,%2,%3}, {%4,%5,%6,%7}, {%8,%9}, {%0,%1,%2,%3};"
        : "+f"(c[0]), "+f"(c[1]), "+f"(c[2]), "+f"(c[3])
        : "r"(a0), "r"(a1), "r"(a2), "r"(a3), "r"(b0), "r"(b1));
}
__device__ __forceinline__ void cp16(void* dst, const void* src) {
    unsigned s = (unsigned)__cvta_generic_to_shared(dst);
    asm volatile("cp.async.cg.shared.global [%0], [%1], 16;" :: "r"(s), "l"(src));
}
// zfill variant: src_size=0 -> smem gets zeros (used for invalid rows)
__device__ __forceinline__ void cp16z(void* dst, const void* src, unsigned sz) {
    unsigned s = (unsigned)__cvta_generic_to_shared(dst);
    asm volatile("cp.async.cg.shared.global [%0], [%1], 16, %2;" :: "r"(s), "l"(src), "r"(sz));
}
#define CP_COMMIT() asm volatile("cp.async.commit_group;" ::)
#define CP_WAIT1()  asm volatile("cp.async.wait_group 1;" ::)
#define CP_WAIT0()  asm volatile("cp.async.wait_group 0;" ::)

// ---------------- fused prep: gate (+tf32 X) | weight convert ----------------
#define GATE_BLKS 2048
#define WCONV_BLKS 2304
__global__ __launch_bounds__(256) void prep_kernel(
    const float* __restrict__ X, const float* __restrict__ Wg, const float* __restrict__ bg,
    const float* __restrict__ Wq, const float* __restrict__ Wk, const float* __restrict__ Wv)
{
    int bx = blockIdx.x;
    if (bx >= GATE_BLKS) {
        int i = (bx - GATE_BLKS) * 256 + threadIdx.x;
        if (i < D_*HD) g_Wqt[i] = f2tf32(Wq[i]);
        g_Wkt[i] = f2tf32(Wk[i]);
        g_Wvt[i] = f2tf32(Wv[i]);
        return;
    }
    int warp = (bx * 256 + threadIdx.x) >> 5;
    int lane = threadIdx.x & 31;
    const float* x = X + (size_t)warp * D_;
    float s[8];
    #pragma unroll
    for (int j = 0; j < 8; j++) s[j] = 0.f;
    for (int i = lane; i < D_; i += 32) {
        float xv = x[i];
        g_Xt[(size_t)warp*D_ + i] = f2tf32(xv);
        float4 w0 = *reinterpret_cast<const float4*>(Wg + (size_t)i*8);
        float4 w1 = *reinterpret_cast<const float4*>(Wg + (size_t)i*8 + 4);
        s[0] = fmaf(xv, w0.x, s[0]); s[1] = fmaf(xv, w0.y, s[1]);
        s[2] = fmaf(xv, w0.z, s[2]); s[3] = fmaf(xv, w0.w, s[3]);
        s[4] = fmaf(xv, w1.x, s[4]); s[5] = fmaf(xv, w1.y, s[5]);
        s[6] = fmaf(xv, w1.z, s[6]); s[7] = fmaf(xv, w1.w, s[7]);
    }
    #pragma unroll
    for (int off = 16; off > 0; off >>= 1)
        #pragma unroll
        for (int j = 0; j < 8; j++)
            s[j] += __shfl_xor_sync(0xffffffffu, s[j], off);
    if (lane == 0) {
        #pragma unroll
        for (int j = 0; j < 8; j++) s[j] += bg[j];
        int i1 = 0;
        #pragma unroll
        for (int j = 1; j < 8; j++) if (s[j] > s[i1]) i1 = j;
        int i2 = -1; float b2 = -1e30f;
        #pragma unroll
        for (int j = 0; j < 8; j++) if (j != i1 && s[j] > b2) { b2 = s[j]; i2 = j; }
        float a1 = 1.f / (1.f + expf(b2 - s[i1]));
        g_m1[warp] = (unsigned char)(i1 + 1);
        g_m2[warp] = (unsigned char)(i2 + 1);
        g_a1[warp] = a1;
        g_a2[warp] = 1.f - a1;
    }
}

// ---------------- pack: 1024 threads, 2 sweep iterations ----------------
__global__ __launch_bounds__(1024) void pack_kernel()
{
    int bm = blockIdx.x;          // 0..63
    int b  = bm >> 3;
    int m  = (bm & 7) + 1;        // 1..8
    __shared__ int wsum[32];
    int tid = threadIdx.x;
    int lane = tid & 31, w = tid >> 5;
    int base = 0;
    int segbase = (b*NM_ + m - 1) * T_;
    for (int t0 = 0; t0 < T_; t0 += 1024) {
        int t = t0 + tid;
        int n = t*B_ + b;
        int sel = 0; float a = 0.f;
        int m1v = g_m1[n], m2v = g_m2[n];
        if      (m1v == m) { sel = 1; a = g_a1[n]; }
        else if (m2v == m) { sel = 1; a = g_a2[n]; }
        int incl = sel;
        #pragma unroll
        for (int off = 1; off < 32; off <<= 1) {
            int u = __shfl_up_sync(0xffffffffu, incl, off);
            if (lane >= off) incl += u;
        }
        if (lane == 31) wsum[w] = incl;
        __syncthreads();
        int woff = 0, tot = 0;
        #pragma unroll
        for (int i = 0; i < 32; i++) { int v = wsum[i]; tot += v; if (i < w) woff += v; }
        if (sel) {
            int pos = base + woff + incl - 1;
            g_tok[segbase + pos] = t;
            g_pa [segbase + pos] = a;
        }
        base += tot;
        __syncthreads();
    }
    if (tid == 0) g_cnt[b*NM_ + m - 1] = base;
}

// ---------------- fused projections: KV tiles (blocks 0..1151) + Q tiles ----------------
#define KV_AP 20
#define KV_BP 136
#define KV_SMEM ((3*128*KV_AP + 3*16*KV_BP + 128) * 4)
#define Q_AP 20
#define Q_BP 72
#define GP_ 68

__device__ __forceinline__ void proj_q_body(unsigned* smem, const float* bq, int bx)
{
    unsigned (*As)[64][Q_AP] = reinterpret_cast<unsigned(*)[64][Q_AP]>(smem);
    unsigned (*Bs)[16][Q_BP] = reinterpret_cast<unsigned(*)[16][Q_BP]>(smem + 3*64*Q_AP);
    int tid = threadIdx.x;
    int m0 = bx * 64;

    int aRow = (tid & 127) >> 1, aOff = (tid & 1) * 8;
    int t2 = tid & 127;
    int bK = t2 >> 3, bj = (t2 & 7) * 8;
    const unsigned* aBase = g_Xt + (size_t)(m0 + aRow)*D_ + aOff;
    const unsigned* bBase = g_Wqt + (size_t)bK*HD + bj;
    bool isA = (tid < 128);

    int lane = tid & 31, gid = lane >> 2, tig = lane & 3;
    int warpId = tid >> 5, wM = warpId & 3, wN = warpId >> 2;

    float c[4][4];
    #pragma unroll
    for (int ni = 0; ni < 4; ni++)
        #pragma unroll
        for (int j = 0; j < 4; j++) c[ni][j] = 0.f;

    #pragma unroll
    for (int s = 0; s < 2; s++) {
        int kt = s * 16;
        if (isA) {
            cp16(&As[s][aRow][aOff],     aBase + kt);
            cp16(&As[s][aRow][aOff + 4], aBase + kt + 4);
        } else {
            cp16(&Bs[s][bK][bj],     bBase + (size_t)kt*HD);
            cp16(&Bs[s][bK][bj + 4], bBase + (size_t)kt*HD + 4);
        }
        CP_COMMIT();
    }

    for (int it = 0; it < 64; it++) {
        CP_WAIT1();
        __syncthreads();
        if (it + 2 < 64) {
            int s = (it + 2) % 3, kt = (it + 2) * 16;
            if (isA) {
                cp16(&As[s][aRow][aOff],     aBase + kt);
                cp16(&As[s][aRow][aOff + 4], aBase + kt + 4);
            } else {
                cp16(&Bs[s][bK][bj],     bBase + (size_t)kt*HD);
                cp16(&Bs[s][bK][bj + 4], bBase + (size_t)kt*HD + 4);
            }
        }
        CP_COMMIT();
        int s = it % 3;
        #pragma unroll
        for (int k0 = 0; k0 < 16; k0 += 8) {
            int r = wM*16 + gid;
            unsigned a0 = As[s][r    ][k0 + tig];
            unsigned a1 = As[s][r + 8][k0 + tig];
            unsigned a2 = As[s][r    ][k0 + tig + 4];
            unsigned a3 = As[s][r + 8][k0 + tig + 4];
            #pragma unroll
            for (int ni = 0; ni < 4; ni++) {
                int cb = wN*32 + ni*8 + gid;
                unsigned b0 = Bs[s][k0 + tig    ][cb];
                unsigned b1 = Bs[s][k0 + tig + 4][cb];
                mma_tf32(c[ni], a0, a1, a2, a3, b0, b1);
            }
        }
    }

    #pragma unroll
    for (int ni = 0; ni < 4; ni++) {
        int colb = wN*32 + ni*8 + tig*2;
        float b0v = bq[colb], b1v = bq[colb + 1];
        int r1 = m0 + wM*16 + gid;
        float2 v1 = make_float2(f2tf32f(c[ni][0] + b0v), f2tf32f(c[ni][1] + b1v));
        *reinterpret_cast<float2*>(g_Q + (size_t)r1*HD + colb) = v1;
        float2 v2 = make_float2(f2tf32f(c[ni][2] + b0v), f2tf32f(c[ni][3] + b1v));
        *reinterpret_cast<float2*>(g_Q + (size_t)(r1 + 8)*HD + colb) = v2;
    }
}

__device__ __forceinline__ void proj_kv_body(unsigned* smem,
    const float* bk, const float* bv, int ci, int m, int b)
{
    int cnt = (m == 0) ? T_ : g_cnt[b*NM_ + m - 1];
    int r0 = ci << 7;
    if (r0 >= cnt) return;
    int L = cnt - r0; if (L > 128) L = 128;

    unsigned (*As)[128][KV_AP] = reinterpret_cast<unsigned(*)[128][KV_AP]>(smem);
    unsigned (*Bs)[16][KV_BP]  = reinterpret_cast<unsigned(*)[16][KV_BP]>(smem + 3*128*KV_AP);
    int* rowIdx = reinterpret_cast<int*>(smem + 3*128*KV_AP + 3*16*KV_BP);

    int tid = threadIdx.x;
    int segbase = (b*NM_ + m - 1) * T_;
    if (tid < 128) {
        int t = 0;
        if (tid < L) t = (m == 0) ? (r0 + tid) : g_tok[segbase + r0 + tid];
        rowIdx[tid] = t*B_ + b;
    }
    __syncthreads();

    int aRow = tid >> 1, aOff = (tid & 1) * 8;
    int bK   = tid >> 4;
    int bj   = (tid & 15) * 8;
    int bHalf = bj >> 6;
    int bo    = bj & 63;
    const unsigned* Wt = bHalf ? g_Wvt : g_Wkt;
    const unsigned* aBase = g_Xt + (size_t)rowIdx[aRow]*D_ + aOff;
    const unsigned* bBase = Wt + (size_t)bK*NKV + m*HD + bo;

    int lane = tid & 31, gid = lane >> 2, tig = lane & 3;
    int warpId = tid >> 5, wM = warpId & 3, wN = warpId >> 2;

    float c[2][8][4];
    #pragma unroll
    for (int mi = 0; mi < 2; mi++)
        #pragma unroll
        for (int ni = 0; ni < 8; ni++)
            #pragma unroll
            for (int j = 0; j < 4; j++) c[mi][ni][j] = 0.f;

    #pragma unroll
    for (int s = 0; s < 2; s++) {
        int kt = s * 16;
        cp16(&As[s][aRow][aOff],     aBase + kt);
        cp16(&As[s][aRow][aOff + 4], aBase + kt + 4);
        cp16(&Bs[s][bK][bj],     bBase + (size_t)kt*NKV);
        cp16(&Bs[s][bK][bj + 4], bBase + (size_t)kt*NKV + 4);
        CP_COMMIT();
    }

    for (int it = 0; it < 64; it++) {
        CP_WAIT1();
        __syncthreads();
        if (it + 2 < 64) {
            int s = (it + 2) % 3, kt = (it + 2) * 16;
            cp16(&As[s][aRow][aOff],     aBase + kt);
            cp16(&As[s][aRow][aOff + 4], aBase + kt + 4);
            cp16(&Bs[s][bK][bj],     bBase + (size_t)kt*NKV);
            cp16(&Bs[s][bK][bj + 4], bBase + (size_t)kt*NKV + 4);
        }
        CP_COMMIT();
        int s = it % 3;
        #pragma unroll
        for (int k0 = 0; k0 < 16; k0 += 8) {
            unsigned a[2][4];
            #pragma unroll
            for (int mi = 0; mi < 2; mi++) {
                int r = wM*32 + mi*16 + gid;
                a[mi][0] = As[s][r    ][k0 + tig];
                a[mi][1] = As[s][r + 8][k0 + tig];
                a[mi][2] = As[s][r    ][k0 + tig + 4];
                a[mi][3] = As[s][r + 8][k0 + tig + 4];
            }
            #pragma unroll
            for (int ni = 0; ni < 8; ni++) {
                int cb = wN*64 + ni*8 + gid;
                unsigned b0 = Bs[s][k0 + tig    ][cb];
                unsigned b1 = Bs[s][k0 + tig + 4][cb];
                mma_tf32(c[0][ni], a[0][0], a[0][1], a[0][2], a[0][3], b0, b1);
                mma_tf32(c[1][ni], a[1][0], a[1][1], a[1][2], a[1][3], b0, b1);
            }
        }
    }

    // ---- global K/V stores ----
    size_t segKV = ((size_t)(b*MP1 + m)*T_ + r0) * HD;
    #pragma unroll
    for (int mi = 0; mi < 2; mi++) {
        #pragma unroll
        for (int ni = 0; ni < 8; ni++) {
            int colb = wN*64 + ni*8 + tig*2;
            int half = colb >> 6;
            int cc = colb & 63;
            const float* bias = half ? bv : bk;
            float b0v = bias[m*HD + cc];
            float b1v = bias[m*HD + cc + 1];
            float* dst = (half ? g_Vp : g_Kp) + segKV + cc;
            int r1 = wM*32 + mi*16 + gid;
            if (r1 < L) {
                float2 v = make_float2(f2tf32f(c[mi][ni][0] + b0v), f2tf32f(c[mi][ni][1] + b1v));
                *reinterpret_cast<float2*>(dst + (size_t)r1*HD) = v;
            }
            int r2 = r1 + 8;
            if (r2 < L) {
                float2 v = make_float2(f2tf32f(c[mi][ni][2] + b0v), f2tf32f(c[mi][ni][3] + b1v));
                *reinterpret_cast<float2*>(dst + (size_t)r2*HD) = v;
            }
        }
    }

    // ---- fused G = K^T V per 64-chunk (reuses pipeline smem) ----
    float* fb = reinterpret_cast<float*>(smem);
    float (*Ks)[GP_] = reinterpret_cast<float(*)[GP_]>(fb);
    float (*Vs)[GP_] = reinterpret_cast<float(*)[GP_]>(fb + 64*GP_);
    int nchunk = (L + 63) >> 6;

    for (int cp = 0; cp < nchunk; cp++) {
        __syncthreads();
        if ((wM >> 1) == cp) {
            int lrBase = (wM & 1) * 32;
            #pragma unroll
            for (int mi = 0; mi < 2; mi++) {
                #pragma unroll
                for (int ni = 0; ni < 8; ni++) {
                    int colb = wN*64 + ni*8 + tig*2;
                    int half = colb >> 6;
                    int cc = colb & 63;
                    const float* bias = half ? bv : bk;
                    float b0v = bias[m*HD + cc];
                    float b1v = bias[m*HD + cc + 1];
                    float (*Ts)[GP_] = half ? Vs : Ks;
                    int lr1 = lrBase + mi*16 + gid;
                    int gr1 = cp*64 + lr1;
                    Ts[lr1][cc]     = (gr1 < L) ? f2tf32f(c[mi][ni][0] + b0v) : 0.f;
                    Ts[lr1][cc + 1] = (gr1 < L) ? f2tf32f(c[mi][ni][1] + b1v) : 0.f;
                    int lr2 = lr1 + 8, gr2 = gr1 + 8;
                    Ts[lr2][cc]     = (gr2 < L) ? f2tf32f(c[mi][ni][2] + b0v) : 0.f;
                    Ts[lr2][cc + 1] = (gr2 < L) ? f2tf32f(c[mi][ni][3] + b1v) : 0.f;
                }
            }
        }
        __syncthreads();

        float g[4][4];
        #pragma unroll
        for (int ni = 0; ni < 4; ni++)
            #pragma unroll
            for (int j = 0; j < 4; j++) g[ni][j] = 0.f;
        int i0 = wM*16, j0 = wN*32;
        #pragma unroll
        for (int k0 = 0; k0 < 64; k0 += 8) {
            unsigned a0 = __float_as_uint(Ks[k0 + tig    ][i0 + gid]);
            unsigned a1 = __float_as_uint(Ks[k0 + tig    ][i0 + gid + 8]);
            unsigned a2 = __float_as_uint(Ks[k0 + tig + 4][i0 + gid]);
            unsigned a3 = __float_as_uint(Ks[k0 + tig + 4][i0 + gid + 8]);
            #pragma unroll
            for (int ni = 0; ni < 4; ni++) {
                int cb = j0 + ni*8 + gid;
                unsigned b0 = __float_as_uint(Vs[k0 + tig    ][cb]);
                unsigned b1 = __float_as_uint(Vs[k0 + tig + 4][cb]);
                mma_tf32(g[ni], a0, a1, a2, a3, b0, b1);
            }
        }
        float* Gp = g_G + (size_t)((b*MP1 + m)*32 + ci*2 + cp) * 4096;
        #pragma unroll
        for (int ni = 0; ni < 4; ni++) {
            int j = j0 + ni*8 + tig*2;
            *reinterpret_cast<float2*>(Gp + (i0 + gid)*64 + j)     = make_float2(g[ni][0], g[ni][1]);
            *reinterpret_cast<float2*>(Gp + (i0 + gid + 8)*64 + j) = make_float2(g[ni][2], g[ni][3]);
        }
    }
}

#define KV_BLKS (16*MP1*B_)
__global__ __launch_bounds__(256, 2) void proj_kernel(
    const float* __restrict__ bq, const float* __restrict__ bk, const float* __restrict__ bv)
{
    extern __shared__ __align__(16) unsigned smem[];
    int bx = blockIdx.x;
    if (bx < KV_BLKS) {
        int ci = bx & 15;
        int rem = bx >> 4;
        int m = rem % MP1, b = rem / MP1;
        proj_kv_body(smem, bk, bv, ci, m, b);
    } else {
        proj_q_body(smem, bq, bx - KV_BLKS);
    }
}

// ---------------- per-segment prefix: 8-deep prefetch, tf32-rounded S ----------------
__global__ __launch_bounds__(256) void prefix_kernel(const float* __restrict__ M0)
{
    int bm = blockIdx.x;               // 0..71
    int b = bm / MP1, m = bm % MP1;
    int cnt = (m == 0) ? T_ : g_cnt[b*NM_ + m - 1];
    int nch = (cnt + 63) >> 6;
    int idx = blockIdx.y * 256 + threadIdx.x;   // 0..4095
    float st = M0[idx];
    const float* Gp = g_G + (size_t)(bm * 32) * 4096 + idx;
    float* Sp = g_S + (size_t)(bm * 32) * 4096 + idx;
    float p[8];
    #pragma unroll
    for (int j = 0; j < 8; j++) p[j] = Gp[(size_t)j * 4096];
    int ci = 0;
    for (; ci + 8 <= nch; ci += 8) {
        size_t off = (size_t)ci * 4096;
        float n[8];
        #pragma unroll
        for (int j = 0; j < 8; j++) n[j] = Gp[off + (size_t)(j + 8) * 4096];
        #pragma unroll
        for (int j = 0; j < 8; j++) {
            Sp[off + (size_t)j * 4096] = f2tf32f(st);
            st += p[j];
        }
        #pragma unroll
        for (int j = 0; j < 8; j++) p[j] = n[j];
    }
    for (; ci < nch; ci++) {
        size_t off = (size_t)ci * 4096;
        Sp[off] = f2tf32f(st);
        st += Gp[off];
    }
}

// ---------------- per-chunk output via tf32 mma: O = tril(QK^T)V + Q S ----------------
#define OP_ 68
#define O_SMEM (4*64*OP_*4)
__global__ __launch_bounds__(256, 2) void chunk_o_kernel(float* __restrict__ out)
{
    int ci = blockIdx.x, m = blockIdx.y, b = blockIdx.z;
    int cnt = (m == 0) ? T_ : g_cnt[b*NM_ + m - 1];
    if ((ci << 6) >= cnt) return;
    int L = cnt - (ci << 6); if (L > 64) L = 64;

    extern __shared__ __align__(16) float sm[];
    float (*QS)[OP_] = reinterpret_cast<float(*)[OP_]>(sm);            // Q
    float (*KP)[OP_] = reinterpret_cast<float(*)[OP_]>(sm + 64*OP_);   // K, then P
    float (*Vs)[OP_] = reinterpret_cast<float(*)[OP_]>(sm + 2*64*OP_); // V
    float (*Ss)[OP_] = reinterpret_cast<float(*)[OP_]>(sm + 3*64*OP_); // S

    int tid = threadIdx.x;
    int segbase = (m == 0) ? 0 : (b*NM_ + m - 1)*T_;
    size_t segp = ((size_t)(b*MP1 + m)*T_ + (ci << 6)) * HD;

    // group 0: Q/K/V via cp.async (zfill for invalid rows)
    {
        int r = tid >> 2, q4 = tid & 3;
        bool valid = r < L;
        const float* qs = g_Q;
        if (valid) {
            int i = (ci << 6) + r;
            int t = (m == 0) ? i : g_tok[segbase + i];
            qs = g_Q + ((size_t)t*B_ + b)*HD;
        }
        const float* ks = g_Kp + segp + (size_t)r*HD;
        const float* vs = g_Vp + segp + (size_t)r*HD;
        unsigned sz = valid ? 16u : 0u;
        #pragma unroll
        for (int j = 0; j < 4; j++) {
            int c = q4*16 + j*4;
            cp16z(&QS[r][c], qs + c, sz);
            cp16z(&KP[r][c], ks + c, sz);
            cp16z(&Vs[r][c], vs + c, sz);
        }
        CP_COMMIT();
    }
    // group 1: S prefetch (needed only at stage 2)
    {
        const float* Sp = g_S + (size_t)((b*MP1 + m)*32 + ci) * 4096;
        #pragma unroll
        for (int i = 0; i < 4; i++) {
            int k = tid + i*256;
            int r = k >> 4, cc = (k & 15) * 4;
            cp16(&Ss[r][cc], Sp + r*64 + cc);
        }
        CP_COMMIT();
    }

    CP_WAIT1();       // Q/K/V ready (group 0 drained; S may still be in flight)
    __syncthreads();

    int lane = tid & 31, gid = lane >> 2, tig = lane & 3;
    int warpId = tid >> 5, wM = warpId & 3, wN = warpId >> 2;
    int r0 = wM*16, n0 = wN*32;

    unsigned aQ[8][4];
    #pragma unroll
    for (int ks = 0; ks < 8; ks++) {
        int k0 = ks*8;
        aQ[ks][0] = __float_as_uint(QS[r0 + gid    ][k0 + tig]);
        aQ[ks][1] = __float_as_uint(QS[r0 + gid + 8][k0 + tig]);
        aQ[ks][2] = __float_as_uint(QS[r0 + gid    ][k0 + tig + 4]);
        aQ[ks][3] = __float_as_uint(QS[r0 + gid + 8][k0 + tig + 4]);
    }

    // stage 1: P = Q K^T
    float p[4][4];
    #pragma unroll
    for (int ni = 0; ni < 4; ni++)
        #pragma unroll
        for (int j = 0; j < 4; j++) p[ni][j] = 0.f;
    #pragma unroll
    for (int ks = 0; ks < 8; ks++) {
        int k0 = ks*8;
        #pragma unroll
        for (int ni = 0; ni < 4; ni++) {
            int cb = n0 + ni*8 + gid;
            unsigned b0 = __float_as_uint(KP[cb][k0 + tig]);
            unsigned b1 = __float_as_uint(KP[cb][k0 + tig + 4]);
            mma_tf32(p[ni], aQ[ks][0], aQ[ks][1], aQ[ks][2], aQ[ks][3], b0, b1);
        }
    }
    __syncthreads();

    // write masked tf32 P over K
    #pragma unroll
    for (int ni = 0; ni < 4; ni++) {
        int col = n0 + ni*8 + tig*2;
        int row1 = r0 + gid, row2 = r0 + gid + 8;
        KP[row1][col]     = (col     <= row1) ? f2tf32f(p[ni][0]) : 0.f;
        KP[row1][col + 1] = (col + 1 <= row1) ? f2tf32f(p[ni][1]) : 0.f;
        KP[row2][col]     = (col     <= row2) ? f2tf32f(p[ni][2]) : 0.f;
        KP[row2][col + 1] = (col + 1 <= row2) ? f2tf32f(p[ni][3]) : 0.f;
    }
    CP_WAIT0();      // S ready
    __syncthreads();

    // stages 2+3: O = P V + Q S
    float o[4][4];
    #pragma unroll
    for (int ni = 0; ni < 4; ni++)
        #pragma unroll
        for (int j = 0; j < 4; j++) o[ni][j] = 0.f;
    #pragma unroll
    for (int ks = 0; ks < 8; ks++) {
        int k0 = ks*8;
        unsigned a0 = __float_as_uint(KP[r0 + gid    ][k0 + tig]);
        unsigned a1 = __float_as_uint(KP[r0 + gid + 8][k0 + tig]);
        unsigned a2 = __float_as_uint(KP[r0 + gid    ][k0 + tig + 4]);
        unsigned a3 = __float_as_uint(KP[r0 + gid + 8][k0 + tig + 4]);
        #pragma unroll
        for (int ni = 0; ni < 4; ni++) {
            int cb = n0 + ni*8 + gid;
            unsigned b0 = __float_as_uint(Vs[k0 + tig    ][cb]);
            unsigned b1 = __float_as_uint(Vs[k0 + tig + 4][cb]);
            mma_tf32(o[ni], a0, a1, a2, a3, b0, b1);
            unsigned s0 = __float_as_uint(Ss[k0 + tig    ][cb]);
            unsigned s1 = __float_as_uint(Ss[k0 + tig + 4][cb]);
            mma_tf32(o[ni], aQ[ks][0], aQ[ks][1], aQ[ks][2], aQ[ks][3], s0, s1);
        }
    }

    // epilogue: out[t,b,col..col+1] += alpha * o
    #pragma unroll
    for (int rr = 0; rr < 2; rr++) {
        int r = r0 + gid + rr*8;
        if (r >= L) continue;
        int idx = (ci << 6) + r;
        int t; float alpha;
        if (m == 0) { t = idx; alpha = 1.f; }
        else        { t = g_tok[segbase + idx]; alpha = g_pa[segbase + idx]; }
        float* op = out + ((size_t)t*B_ + b)*HD;
        #pragma unroll
        for (int ni = 0; ni < 4; ni++) {
            int col = n0 + ni*8 + tig*2;
            atomicAdd(op + col,     alpha * o[ni][rr*2]);
            atomicAdd(op + col + 1, alpha * o[ni][rr*2 + 1]);
        }
    }
}

// ---------------- launch ----------------
extern "C" void kernel_launch(void* const* d_in, const int* in_sizes, int n_in,
                              void* d_out, int out_size)
{
    const float* X  = (const float*)d_in[0];
    const float* M0 = (const float*)d_in[1];
    const float* Wq = (const float*)d_in[2];
    const float* bq = (const float*)d_in[3];
    const float* Wk = (const float*)d_in[4];
    const float* bk = (const float*)d_in[5];
    const float* Wv = (const float*)d_in[6];
    const float* bv = (const float*)d_in[7];
    const float* Wg = (const float*)d_in[8];
    const float* bg = (const float*)d_in[9];
    float* out = (float*)d_out;

    cudaFuncSetAttribute(proj_kernel,
                         cudaFuncAttributeMaxDynamicSharedMemorySize, KV_SMEM);
    cudaFuncSetAttribute(chunk_o_kernel,
                         cudaFuncAttributeMaxDynamicSharedMemorySize, O_SMEM);

    cudaMemsetAsync(out, 0, (size_t)NT * HD * sizeof(float));
    prep_kernel<<<GATE_BLKS + WCONV_BLKS, 256>>>(X, Wg, bg, Wq, Wk, Wv);
    pack_kernel<<<64, 1024>>>();
    proj_kernel<<<KV_BLKS + 256, 256, KV_SMEM>>>(bq, bk, bv);
    prefix_kernel<<<dim3(B_*MP1, 16), 256>>>(M0);
    chunk_o_kernel<<<dim3(32, MP1, B_), 256, O_SMEM>>>(out);
}

// round 16
// speedup vs baseline: 1.6780x; 1.0367x over previous
#include <cuda_runtime.h>
#include <math.h>

#define T_   2048
#define B_   8
#define D_   1024
#define HD   64      // d
#define NM_  8
#define MP1  9
#define NT   (T_*B_)     // 16384 tokens
#define NKV  576         // Mp1 * d

// ---------------- static device scratch ----------------
__device__ float g_Q[NT*HD];                                // tf32-valued fp32
__device__ float g_Kp[(size_t)B_*MP1*T_*HD];                // packed K per (b,m), tf32-valued
__device__ float g_Vp[(size_t)B_*MP1*T_*HD];                // packed V per (b,m), tf32-valued
#define NSLOT (B_*MP1*32)
__device__ float g_G[(size_t)(NSLOT + 16)*HD*HD];           // per-chunk K^T V (+16 slot pad for prefetch)
__device__ float g_S[(size_t)NSLOT*HD*HD];                  // chunk start state (tf32-valued)
__device__ int   g_tok[B_*NM_*T_];
__device__ float g_pa [B_*NM_*T_];
__device__ int   g_cnt[B_*NM_];
__device__ unsigned char g_m1[NT], g_m2[NT];
__device__ float g_a1[NT], g_a2[NT];
__device__ unsigned g_Xt[(size_t)NT*D_];                    // X in tf32 bits
__device__ unsigned g_Wqt[D_*HD];
__device__ unsigned g_Wkt[D_*NKV];
__device__ unsigned g_Wvt[D_*NKV];

// ---------------- tf32 mma helpers ----------------
__device__ __forceinline__ unsigned f2tf32(float f) {
    unsigned u;
    asm("cvt.rna.tf32.f32 %0, %1;" : "=r"(u) : "f"(f));
    return u;
}
__device__ __forceinline__ float f2tf32f(float f) { return __uint_as_float(f2tf32(f)); }
__device__ __forceinline__ void mma_tf32(float* c,
    unsigned a0, unsigned a1, unsigned a2, unsigned a3,
    unsigned b0, unsigned b1)
{
    asm volatile(
        "mma.sync.aligned.m16n8k8.row.col.f32.tf32.tf32.f32 "
        "{%0,%1,%2,%3}, {%4,%5,%6,%7}, {%8,%9}, {%0,%1,%2,%3};"
        : "+f"(c[0]), "+f"(c[1]), "+f"(c[2]), "+f"(c[3])
        : "r"(a0), "r"(a1), "r"(a2), "r"(a3), "r"(b0), "r"(b1));
}
__device__ __forceinline__ void cp16(void* dst, const void* src) {
    unsigned s = (unsigned)__cvta_generic_to_shared(dst);
    asm volatile("cp.async.cg.shared.global [%0], [%1], 16;" :: "r"(s), "l"(src));
}
// zfill variant: src_size=0 -> smem gets zeros (used for invalid rows)
__device__ __forceinline__ void cp16z(void* dst, const void* src, unsigned sz) {
    unsigned s = (unsigned)__cvta_generic_to_shared(dst);
    asm volatile("cp.async.cg.shared.global [%0], [%1], 16, %2;" :: "r"(s), "l"(src), "r"(sz));
}
#define CP_COMMIT() asm volatile("cp.async.commit_group;" ::)
#define CP_WAIT1()  asm volatile("cp.async.wait_group 1;" ::)
#define CP_WAIT0()  asm volatile("cp.async.wait_group 0;" ::)

// ---------------- fused prep: gate 2 tokens/warp (+tf32 X) | zero out | weight convert ----------------
#define GATE_BLKS 1024
#define ZERO_BLKS 1024
#define WCONV_BLKS 2304
__global__ __launch_bounds__(256) void prep_kernel(
    const float* __restrict__ X, const float* __restrict__ Wg, const float* __restrict__ bg,
    const float* __restrict__ Wq, const float* __restrict__ Wk, const float* __restrict__ Wv,
    float* __restrict__ out)
{
    int bx = blockIdx.x;
    if (bx >= GATE_BLKS) {
        if (bx < GATE_BLKS + ZERO_BLKS) {
            int i = (bx - GATE_BLKS) * 256 + threadIdx.x;
            reinterpret_cast<float4*>(out)[i] = make_float4(0.f, 0.f, 0.f, 0.f);
        } else {
            int i = (bx - GATE_BLKS - ZERO_BLKS) * 256 + threadIdx.x;
            if (i < D_*HD) g_Wqt[i] = f2tf32(Wq[i]);
            g_Wkt[i] = f2tf32(Wk[i]);
            g_Wvt[i] = f2tf32(Wv[i]);
        }
        return;
    }
    int wgid = (bx * 256 + threadIdx.x) >> 5;      // 0..8191, handles tokens 2*wgid, 2*wgid+1
    int lane = threadIdx.x & 31;
    int n0 = 2*wgid, n1 = 2*wgid + 1;
    const float* x0 = X + (size_t)n0 * D_;
    const float* x1 = X + (size_t)n1 * D_;
    float s0[8], s1[8];
    #pragma unroll
    for (int j = 0; j < 8; j++) { s0[j] = 0.f; s1[j] = 0.f; }
    for (int i = lane; i < D_; i += 32) {
        float xa = x0[i];
        float xb = x1[i];
        g_Xt[(size_t)n0*D_ + i] = f2tf32(xa);
        g_Xt[(size_t)n1*D_ + i] = f2tf32(xb);
        float4 w0 = *reinterpret_cast<const float4*>(Wg + (size_t)i*8);
        float4 w1 = *reinterpret_cast<const float4*>(Wg + (size_t)i*8 + 4);
        s0[0] = fmaf(xa, w0.x, s0[0]); s0[1] = fmaf(xa, w0.y, s0[1]);
        s0[2] = fmaf(xa, w0.z, s0[2]); s0[3] = fmaf(xa, w0.w, s0[3]);
        s0[4] = fmaf(xa, w1.x, s0[4]); s0[5] = fmaf(xa, w1.y, s0[5]);
        s0[6] = fmaf(xa, w1.z, s0[6]); s0[7] = fmaf(xa, w1.w, s0[7]);
        s1[0] = fmaf(xb, w0.x, s1[0]); s1[1] = fmaf(xb, w0.y, s1[1]);
        s1[2] = fmaf(xb, w0.z, s1[2]); s1[3] = fmaf(xb, w0.w, s1[3]);
        s1[4] = fmaf(xb, w1.x, s1[4]); s1[5] = fmaf(xb, w1.y, s1[5]);
        s1[6] = fmaf(xb, w1.z, s1[6]); s1[7] = fmaf(xb, w1.w, s1[7]);
    }
    #pragma unroll
    for (int off = 16; off > 0; off >>= 1)
        #pragma unroll
        for (int j = 0; j < 8; j++) {
            s0[j] += __shfl_xor_sync(0xffffffffu, s0[j], off);
            s1[j] += __shfl_xor_sync(0xffffffffu, s1[j], off);
        }
    if (lane == 0) {
        #pragma unroll
        for (int tk = 0; tk < 2; tk++) {
            float* s = tk ? s1 : s0;
            int n = tk ? n1 : n0;
            #pragma unroll
            for (int j = 0; j < 8; j++) s[j] += bg[j];
            int i1 = 0;
            #pragma unroll
            for (int j = 1; j < 8; j++) if (s[j] > s[i1]) i1 = j;
            int i2 = -1; float b2 = -1e30f;
            #pragma unroll
            for (int j = 0; j < 8; j++) if (j != i1 && s[j] > b2) { b2 = s[j]; i2 = j; }
            float a1 = 1.f / (1.f + expf(b2 - s[i1]));
            g_m1[n] = (unsigned char)(i1 + 1);
            g_m2[n] = (unsigned char)(i2 + 1);
            g_a1[n] = a1;
            g_a2[n] = 1.f - a1;
        }
    }
}

// ---------------- pack: 1024 threads, 2 sweep iterations ----------------
__global__ __launch_bounds__(1024) void pack_kernel()
{
    int bm = blockIdx.x;          // 0..63
    int b  = bm >> 3;
    int m  = (bm & 7) + 1;        // 1..8
    __shared__ int wsum[32];
    int tid = threadIdx.x;
    int lane = tid & 31, w = tid >> 5;
    int base = 0;
    int segbase = (b*NM_ + m - 1) * T_;
    for (int t0 = 0; t0 < T_; t0 += 1024) {
        int t = t0 + tid;
        int n = t*B_ + b;
        int sel = 0; float a = 0.f;
        int m1v = g_m1[n], m2v = g_m2[n];
        if      (m1v == m) { sel = 1; a = g_a1[n]; }
        else if (m2v == m) { sel = 1; a = g_a2[n]; }
        int incl = sel;
        #pragma unroll
        for (int off = 1; off < 32; off <<= 1) {
            int u = __shfl_up_sync(0xffffffffu, incl, off);
            if (lane >= off) incl += u;
        }
        if (lane == 31) wsum[w] = incl;
        __syncthreads();
        int woff = 0, tot = 0;
        #pragma unroll
        for (int i = 0; i < 32; i++) { int v = wsum[i]; tot += v; if (i < w) woff += v; }
        if (sel) {
            int pos = base + woff + incl - 1;
            g_tok[segbase + pos] = t;
            g_pa [segbase + pos] = a;
        }
        base += tot;
        __syncthreads();
    }
    if (tid == 0) g_cnt[b*NM_ + m - 1] = base;
}

// ---------------- fused projections: KV tiles (blocks 0..1151) + Q tiles ----------------
#define KV_AP 20
#define KV_BP 136
#define KV_SMEM ((3*128*KV_AP + 3*16*KV_BP + 128) * 4)
#define Q_AP 20
#define Q_BP 72
#define GP_ 68

__device__ __forceinline__ void proj_q_body(unsigned* smem, const float* bq, int bx)
{
    unsigned (*As)[64][Q_AP] = reinterpret_cast<unsigned(*)[64][Q_AP]>(smem);
    unsigned (*Bs)[16][Q_BP] = reinterpret_cast<unsigned(*)[16][Q_BP]>(smem + 3*64*Q_AP);
    int tid = threadIdx.x;
    int m0 = bx * 64;

    int aRow = (tid & 127) >> 1, aOff = (tid & 1) * 8;
    int t2 = tid & 127;
    int bK = t2 >> 3, bj = (t2 & 7) * 8;
    const unsigned* aBase = g_Xt + (size_t)(m0 + aRow)*D_ + aOff;
    const unsigned* bBase = g_Wqt + (size_t)bK*HD + bj;
    bool isA = (tid < 128);

    int lane = tid & 31, gid = lane >> 2, tig = lane & 3;
    int warpId = tid >> 5, wM = warpId & 3, wN = warpId >> 2;

    float c[4][4];
    #pragma unroll
    for (int ni = 0; ni < 4; ni++)
        #pragma unroll
        for (int j = 0; j < 4; j++) c[ni][j] = 0.f;

    #pragma unroll
    for (int s = 0; s < 2; s++) {
        int kt = s * 16;
        if (isA) {
            cp16(&As[s][aRow][aOff],     aBase + kt);
            cp16(&As[s][aRow][aOff + 4], aBase + kt + 4);
        } else {
            cp16(&Bs[s][bK][bj],     bBase + (size_t)kt*HD);
            cp16(&Bs[s][bK][bj + 4], bBase + (size_t)kt*HD + 4);
        }
        CP_COMMIT();
    }

    for (int it = 0; it < 64; it++) {
        CP_WAIT1();
        __syncthreads();
        if (it + 2 < 64) {
            int s = (it + 2) % 3, kt = (it + 2) * 16;
            if (isA) {
                cp16(&As[s][aRow][aOff],     aBase + kt);
                cp16(&As[s][aRow][aOff + 4], aBase + kt + 4);
            } else {
                cp16(&Bs[s][bK][bj],     bBase + (size_t)kt*HD);
                cp16(&Bs[s][bK][bj + 4], bBase + (size_t)kt*HD + 4);
            }
        }
        CP_COMMIT();
        int s = it % 3;
        #pragma unroll
        for (int k0 = 0; k0 < 16; k0 += 8) {
            int r = wM*16 + gid;
            unsigned a0 = As[s][r    ][k0 + tig];
            unsigned a1 = As[s][r + 8][k0 + tig];
            unsigned a2 = As[s][r    ][k0 + tig + 4];
            unsigned a3 = As[s][r + 8][k0 + tig + 4];
            #pragma unroll
            for (int ni = 0; ni < 4; ni++) {
                int cb = wN*32 + ni*8 + gid;
                unsigned b0 = Bs[s][k0 + tig    ][cb];
                unsigned b1 = Bs[s][k0 + tig + 4][cb];
                mma_tf32(c[ni], a0, a1, a2, a3, b0, b1);
            }
        }
    }

    #pragma unroll
    for (int ni = 0; ni < 4; ni++) {
        int colb = wN*32 + ni*8 + tig*2;
        float b0v = bq[colb], b1v = bq[colb + 1];
        int r1 = m0 + wM*16 + gid;
        float2 v1 = make_float2(f2tf32f(c[ni][0] + b0v), f2tf32f(c[ni][1] + b1v));
        *reinterpret_cast<float2*>(g_Q + (size_t)r1*HD + colb) = v1;
        float2 v2 = make_float2(f2tf32f(c[ni][2] + b0v), f2tf32f(c[ni][3] + b1v));
        *reinterpret_cast<float2*>(g_Q + (size_t)(r1 + 8)*HD + colb) = v2;
    }
}

__device__ __forceinline__ void proj_kv_body(unsigned* smem,
    const float* bk, const float* bv, int ci, int m, int b)
{
    int cnt = (m == 0) ? T_ : g_cnt[b*NM_ + m - 1];
    int r0 = ci << 7;
    if (r0 >= cnt) return;
    int L = cnt - r0; if (L > 128) L = 128;

    unsigned (*As)[128][KV_AP] = reinterpret_cast<unsigned(*)[128][KV_AP]>(smem);
    unsigned (*Bs)[16][KV_BP]  = reinterpret_cast<unsigned(*)[16][KV_BP]>(smem + 3*128*KV_AP);
    int* rowIdx = reinterpret_cast<int*>(smem + 3*128*KV_AP + 3*16*KV_BP);

    int tid = threadIdx.x;
    int segbase = (b*NM_ + m - 1) * T_;
    if (tid < 128) {
        int t = 0;
        if (tid < L) t = (m == 0) ? (r0 + tid) : g_tok[segbase + r0 + tid];
        rowIdx[tid] = t*B_ + b;
    }
    __syncthreads();

    int aRow = tid >> 1, aOff = (tid & 1) * 8;
    int bK   = tid >> 4;
    int bj   = (tid & 15) * 8;
    int bHalf = bj >> 6;
    int bo    = bj & 63;
    const unsigned* Wt = bHalf ? g_Wvt : g_Wkt;
    const unsigned* aBase = g_Xt + (size_t)rowIdx[aRow]*D_ + aOff;
    const unsigned* bBase = Wt + (size_t)bK*NKV + m*HD + bo;

    int lane = tid & 31, gid = lane >> 2, tig = lane & 3;
    int warpId = tid >> 5, wM = warpId & 3, wN = warpId >> 2;

    float c[2][8][4];
    #pragma unroll
    for (int mi = 0; mi < 2; mi++)
        #pragma unroll
        for (int ni = 0; ni < 8; ni++)
            #pragma unroll
            for (int j = 0; j < 4; j++) c[mi][ni][j] = 0.f;

    #pragma unroll
    for (int s = 0; s < 2; s++) {
        int kt = s * 16;
        cp16(&As[s][aRow][aOff],     aBase + kt);
        cp16(&As[s][aRow][aOff + 4], aBase + kt + 4);
        cp16(&Bs[s][bK][bj],     bBase + (size_t)kt*NKV);
        cp16(&Bs[s][bK][bj + 4], bBase + (size_t)kt*NKV + 4);
        CP_COMMIT();
    }

    for (int it = 0; it < 64; it++) {
        CP_WAIT1();
        __syncthreads();
        if (it + 2 < 64) {
            int s = (it + 2) % 3, kt = (it + 2) * 16;
            cp16(&As[s][aRow][aOff],     aBase + kt);
            cp16(&As[s][aRow][aOff + 4], aBase + kt + 4);
            cp16(&Bs[s][bK][bj],     bBase + (size_t)kt*NKV);
            cp16(&Bs[s][bK][bj + 4], bBase + (size_t)kt*NKV + 4);
        }
        CP_COMMIT();
        int s = it % 3;
        #pragma unroll
        for (int k0 = 0; k0 < 16; k0 += 8) {
            unsigned a[2][4];
            #pragma unroll
            for (int mi = 0; mi < 2; mi++) {
                int r = wM*32 + mi*16 + gid;
                a[mi][0] = As[s][r    ][k0 + tig];
                a[mi][1] = As[s][r + 8][k0 + tig];
                a[mi][2] = As[s][r    ][k0 + tig + 4];
                a[mi][3] = As[s][r + 8][k0 + tig + 4];
            }
            #pragma unroll
            for (int ni = 0; ni < 8; ni++) {
                int cb = wN*64 + ni*8 + gid;
                unsigned b0 = Bs[s][k0 + tig    ][cb];
                unsigned b1 = Bs[s][k0 + tig + 4][cb];
                mma_tf32(c[0][ni], a[0][0], a[0][1], a[0][2], a[0][3], b0, b1);
                mma_tf32(c[1][ni], a[1][0], a[1][1], a[1][2], a[1][3], b0, b1);
            }
        }
    }

    // ---- global K/V stores ----
    size_t segKV = ((size_t)(b*MP1 + m)*T_ + r0) * HD;
    #pragma unroll
    for (int mi = 0; mi < 2; mi++) {
        #pragma unroll
        for (int ni = 0; ni < 8; ni++) {
            int colb = wN*64 + ni*8 + tig*2;
            int half = colb >> 6;
            int cc = colb & 63;
            const float* bias = half ? bv : bk;
            float b0v = bias[m*HD + cc];
            float b1v = bias[m*HD + cc + 1];
            float* dst = (half ? g_Vp : g_Kp) + segKV + cc;
            int r1 = wM*32 + mi*16 + gid;
            if (r1 < L) {
                float2 v = make_float2(f2tf32f(c[mi][ni][0] + b0v), f2tf32f(c[mi][ni][1] + b1v));
                *reinterpret_cast<float2*>(dst + (size_t)r1*HD) = v;
            }
            int r2 = r1 + 8;
            if (r2 < L) {
                float2 v = make_float2(f2tf32f(c[mi][ni][2] + b0v), f2tf32f(c[mi][ni][3] + b1v));
                *reinterpret_cast<float2*>(dst + (size_t)r2*HD) = v;
            }
        }
    }

    // ---- fused G = K^T V per 64-chunk (reuses pipeline smem) ----
    float* fb = reinterpret_cast<float*>(smem);
    float (*Ks)[GP_] = reinterpret_cast<float(*)[GP_]>(fb);
    float (*Vs)[GP_] = reinterpret_cast<float(*)[GP_]>(fb + 64*GP_);
    int nchunk = (L + 63) >> 6;

    for (int cp = 0; cp < nchunk; cp++) {
        __syncthreads();
        if ((wM >> 1) == cp) {
            int lrBase = (wM & 1) * 32;
            #pragma unroll
            for (int mi = 0; mi < 2; mi++) {
                #pragma unroll
                for (int ni = 0; ni < 8; ni++) {
                    int colb = wN*64 + ni*8 + tig*2;
                    int half = colb >> 6;
                    int cc = colb & 63;
                    const float* bias = half ? bv : bk;
                    float b0v = bias[m*HD + cc];
                    float b1v = bias[m*HD + cc + 1];
                    float (*Ts)[GP_] = half ? Vs : Ks;
                    int lr1 = lrBase + mi*16 + gid;
                    int gr1 = cp*64 + lr1;
                    Ts[lr1][cc]     = (gr1 < L) ? f2tf32f(c[mi][ni][0] + b0v) : 0.f;
                    Ts[lr1][cc + 1] = (gr1 < L) ? f2tf32f(c[mi][ni][1] + b1v) : 0.f;
                    int lr2 = lr1 + 8, gr2 = gr1 + 8;
                    Ts[lr2][cc]     = (gr2 < L) ? f2tf32f(c[mi][ni][2] + b0v) : 0.f;
                    Ts[lr2][cc + 1] = (gr2 < L) ? f2tf32f(c[mi][ni][3] + b1v) : 0.f;
                }
            }
        }
        __syncthreads();

        float g[4][4];
        #pragma unroll
        for (int ni = 0; ni < 4; ni++)
            #pragma unroll
            for (int j = 0; j < 4; j++) g[ni][j] = 0.f;
        int i0 = wM*16, j0 = wN*32;
        #pragma unroll
        for (int k0 = 0; k0 < 64; k0 += 8) {
            unsigned a0 = __float_as_uint(Ks[k0 + tig    ][i0 + gid]);
            unsigned a1 = __float_as_uint(Ks[k0 + tig    ][i0 + gid + 8]);
            unsigned a2 = __float_as_uint(Ks[k0 + tig + 4][i0 + gid]);
            unsigned a3 = __float_as_uint(Ks[k0 + tig + 4][i0 + gid + 8]);
            #pragma unroll
            for (int ni = 0; ni < 4; ni++) {
                int cb = j0 + ni*8 + gid;
                unsigned b0 = __float_as_uint(Vs[k0 + tig    ][cb]);
                unsigned b1 = __float_as_uint(Vs[k0 + tig + 4][cb]);
                mma_tf32(g[ni], a0, a1, a2, a3, b0, b1);
            }
        }
        float* Gp = g_G + (size_t)((b*MP1 + m)*32 + ci*2 + cp) * 4096;
        #pragma unroll
        for (int ni = 0; ni < 4; ni++) {
            int j = j0 + ni*8 + tig*2;
            *reinterpret_cast<float2*>(Gp + (i0 + gid)*64 + j)     = make_float2(g[ni][0], g[ni][1]);
            *reinterpret_cast<float2*>(Gp + (i0 + gid + 8)*64 + j) = make_float2(g[ni][2], g[ni][3]);
        }
    }
}

#define KV_BLKS (16*MP1*B_)
__global__ __launch_bounds__(256, 2) void proj_kernel(
    const float* __restrict__ bq, const float* __restrict__ bk, const float* __restrict__ bv)
{
    extern __shared__ __align__(16) unsigned smem[];
    int bx = blockIdx.x;
    if (bx < KV_BLKS) {
        int ci = bx & 15;
        int rem = bx >> 4;
        int m = rem % MP1, b = rem / MP1;
        proj_kv_body(smem, bk, bv, ci, m, b);
    } else {
        proj_q_body(smem, bq, bx - KV_BLKS);
    }
}

// ---------------- per-segment prefix: 8-deep prefetch, tf32-rounded S ----------------
__global__ __launch_bounds__(256) void prefix_kernel(const float* __restrict__ M0)
{
    int bm = blockIdx.x;               // 0..71
    int b = bm / MP1, m = bm % MP1;
    int cnt = (m == 0) ? T_ : g_cnt[b*NM_ + m - 1];
    int nch = (cnt + 63) >> 6;
    int idx = blockIdx.y * 256 + threadIdx.x;   // 0..4095
    float st = M0[idx];
    const float* Gp = g_G + (size_t)(bm * 32) * 4096 + idx;
    float* Sp = g_S + (size_t)(bm * 32) * 4096 + idx;
    float p[8];
    #pragma unroll
    for (int j = 0; j < 8; j++) p[j] = Gp[(size_t)j * 4096];
    int ci = 0;
    for (; ci + 8 <= nch; ci += 8) {
        size_t off = (size_t)ci * 4096;
        float n[8];
        #pragma unroll
        for (int j = 0; j < 8; j++) n[j] = Gp[off + (size_t)(j + 8) * 4096];
        #pragma unroll
        for (int j = 0; j < 8; j++) {
            Sp[off + (size_t)j * 4096] = f2tf32f(st);
            st += p[j];
        }
        #pragma unroll
        for (int j = 0; j < 8; j++) p[j] = n[j];
    }
    for (; ci < nch; ci++) {
        size_t off = (size_t)ci * 4096;
        Sp[off] = f2tf32f(st);
        st += Gp[off];
    }
}

// ---------------- per-chunk output via tf32 mma: O = tril(QK^T)V + Q S ----------------
#define OP_ 68
#define O_SMEM (4*64*OP_*4)
__global__ __launch_bounds__(256, 2) void chunk_o_kernel(float* __restrict__ out)
{
    int ci = blockIdx.x, m = blockIdx.y, b = blockIdx.z;
    int cnt = (m == 0) ? T_ : g_cnt[b*NM_ + m - 1];
    if ((ci << 6) >= cnt) return;
    int L = cnt - (ci << 6); if (L > 64) L = 64;

    extern __shared__ __align__(16) float sm[];
    float (*QS)[OP_] = reinterpret_cast<float(*)[OP_]>(sm);            // Q
    float (*KP)[OP_] = reinterpret_cast<float(*)[OP_]>(sm + 64*OP_);   // K, then P
    float (*Vs)[OP_] = reinterpret_cast<float(*)[OP_]>(sm + 2*64*OP_); // V
    float (*Ss)[OP_] = reinterpret_cast<float(*)[OP_]>(sm + 3*64*OP_); // S

    int tid = threadIdx.x;
    int segbase = (m == 0) ? 0 : (b*NM_ + m - 1)*T_;
    size_t segp = ((size_t)(b*MP1 + m)*T_ + (ci << 6)) * HD;

    // group 0: Q/K/V via cp.async (zfill for invalid rows)
    {
        int r = tid >> 2, q4 = tid & 3;
        bool valid = r < L;
        const float* qs = g_Q;
        if (valid) {
            int i = (ci << 6) + r;
            int t = (m == 0) ? i : g_tok[segbase + i];
            qs = g_Q + ((size_t)t*B_ + b)*HD;
        }
        const float* ks = g_Kp + segp + (size_t)r*HD;
        const float* vs = g_Vp + segp + (size_t)r*HD;
        unsigned sz = valid ? 16u : 0u;
        #pragma unroll
        for (int j = 0; j < 4; j++) {
            int c = q4*16 + j*4;
            cp16z(&QS[r][c], qs + c, sz);
            cp16z(&KP[r][c], ks + c, sz);
            cp16z(&Vs[r][c], vs + c, sz);
        }
        CP_COMMIT();
    }
    // group 1: S prefetch (needed only at stage 2)
    {
        const float* Sp = g_S + (size_t)((b*MP1 + m)*32 + ci) * 4096;
        #pragma unroll
        for (int i = 0; i < 4; i++) {
            int k = tid + i*256;
            int r = k >> 4, cc = (k & 15) * 4;
            cp16(&Ss[r][cc], Sp + r*64 + cc);
        }
        CP_COMMIT();
    }

    CP_WAIT1();       // Q/K/V ready (group 0 drained; S may still be in flight)
    __syncthreads();

    int lane = tid & 31, gid = lane >> 2, tig = lane & 3;
    int warpId = tid >> 5, wM = warpId & 3, wN = warpId >> 2;
    int r0 = wM*16, n0 = wN*32;

    unsigned aQ[8][4];
    #pragma unroll
    for (int ks = 0; ks < 8; ks++) {
        int k0 = ks*8;
        aQ[ks][0] = __float_as_uint(QS[r0 + gid    ][k0 + tig]);
        aQ[ks][1] = __float_as_uint(QS[r0 + gid + 8][k0 + tig]);
        aQ[ks][2] = __float_as_uint(QS[r0 + gid    ][k0 + tig + 4]);
        aQ[ks][3] = __float_as_uint(QS[r0 + gid + 8][k0 + tig + 4]);
    }

    // stage 1: P = Q K^T
    float p[4][4];
    #pragma unroll
    for (int ni = 0; ni < 4; ni++)
        #pragma unroll
        for (int j = 0; j < 4; j++) p[ni][j] = 0.f;
    #pragma unroll
    for (int ks = 0; ks < 8; ks++) {
        int k0 = ks*8;
        #pragma unroll
        for (int ni = 0; ni < 4; ni++) {
            int cb = n0 + ni*8 + gid;
            unsigned b0 = __float_as_uint(KP[cb][k0 + tig]);
            unsigned b1 = __float_as_uint(KP[cb][k0 + tig + 4]);
            mma_tf32(p[ni], aQ[ks][0], aQ[ks][1], aQ[ks][2], aQ[ks][3], b0, b1);
        }
    }
    __syncthreads();

    // write masked tf32 P over K
    #pragma unroll
    for (int ni = 0; ni < 4; ni++) {
        int col = n0 + ni*8 + tig*2;
        int row1 = r0 + gid, row2 = r0 + gid + 8;
        KP[row1][col]     = (col     <= row1) ? f2tf32f(p[ni][0]) : 0.f;
        KP[row1][col + 1] = (col + 1 <= row1) ? f2tf32f(p[ni][1]) : 0.f;
        KP[row2][col]     = (col     <= row2) ? f2tf32f(p[ni][2]) : 0.f;
        KP[row2][col + 1] = (col + 1 <= row2) ? f2tf32f(p[ni][3]) : 0.f;
    }
    CP_WAIT0();      // S ready
    __syncthreads();

    // stages 2+3: O = P V + Q S
    float o[4][4];
    #pragma unroll
    for (int ni = 0; ni < 4; ni++)
        #pragma unroll
        for (int j = 0; j < 4; j++) o[ni][j] = 0.f;
    #pragma unroll
    for (int ks = 0; ks < 8; ks++) {
        int k0 = ks*8;
        unsigned a0 = __float_as_uint(KP[r0 + gid    ][k0 + tig]);
        unsigned a1 = __float_as_uint(KP[r0 + gid + 8][k0 + tig]);
        unsigned a2 = __float_as_uint(KP[r0 + gid    ][k0 + tig + 4]);
        unsigned a3 = __float_as_uint(KP[r0 + gid + 8][k0 + tig + 4]);
        #pragma unroll
        for (int ni = 0; ni < 4; ni++) {
            int cb = n0 + ni*8 + gid;
            unsigned b0 = __float_as_uint(Vs[k0 + tig    ][cb]);
            unsigned b1 = __float_as_uint(Vs[k0 + tig + 4][cb]);
            mma_tf32(o[ni], a0, a1, a2, a3, b0, b1);
            unsigned s0 = __float_as_uint(Ss[k0 + tig    ][cb]);
            unsigned s1 = __float_as_uint(Ss[k0 + tig + 4][cb]);
            mma_tf32(o[ni], aQ[ks][0], aQ[ks][1], aQ[ks][2], aQ[ks][3], s0, s1);
        }
    }

    // epilogue: out[t,b,col..col+1] += alpha * o
    #pragma unroll
    for (int rr = 0; rr < 2; rr++) {
        int r = r0 + gid + rr*8;
        if (r >= L) continue;
        int idx = (ci << 6) + r;
        int t; float alpha;
        if (m == 0) { t = idx; alpha = 1.f; }
        else        { t = g_tok[segbase + idx]; alpha = g_pa[segbase + idx]; }
        float* op = out + ((size_t)t*B_ + b)*HD;
        #pragma unroll
        for (int ni = 0; ni < 4; ni++) {
            int col = n0 + ni*8 + tig*2;
            atomicAdd(op + col,     alpha * o[ni][rr*2]);
            atomicAdd(op + col + 1, alpha * o[ni][rr*2 + 1]);
        }
    }
}

// ---------------- launch ----------------
extern "C" void kernel_launch(void* const* d_in, const int* in_sizes, int n_in,
                              void* d_out, int out_size)
{
    const float* X  = (const float*)d_in[0];
    const float* M0 = (const float*)d_in[1];
    const float* Wq = (const float*)d_in[2];
    const float* bq = (const float*)d_in[3];
    const float* Wk = (const float*)d_in[4];
    const float* bk = (const float*)d_in[5];
    const float* Wv = (const float*)d_in[6];
    const float* bv = (const float*)d_in[7];
    const float* Wg = (const float*)d_in[8];
    const float* bg = (const float*)d_in[9];
    float* out = (float*)d_out;

    cudaFuncSetAttribute(proj_kernel,
                         cudaFuncAttributeMaxDynamicSharedMemorySize, KV_SMEM);
    cudaFuncSetAttribute(chunk_o_kernel,
                         cudaFuncAttributeMaxDynamicSharedMemorySize, O_SMEM);

    prep_kernel<<<GATE_BLKS + ZERO_BLKS + WCONV_BLKS, 256>>>(X, Wg, bg, Wq, Wk, Wv, out);
    pack_kernel<<<64, 1024>>>();
    proj_kernel<<<KV_BLKS + 256, 256, KV_SMEM>>>(bq, bk, bv);
    prefix_kernel<<<dim3(B_*MP1, 16), 256>>>(M0);
    chunk_o_kernel<<<dim3(32, MP1, B_), 256, O_SMEM>>>(out);
}